// round 5
// baseline (speedup 1.0000x reference)
#include <cuda_runtime.h>

#define NNODE 17
#define TPB   272      // 17 nodes x 16 graphs
#define NG    16       // graphs per block

typedef unsigned long long u64;

// packed fp32x2 FMA (Blackwell); ptxas never auto-fuses this from C++
__device__ __forceinline__ u64 ffma2(u64 a, u64 b, u64 c) {
    u64 d;
    asm("fma.rn.f32x2 %0, %1, %2, %3;" : "=l"(d) : "l"(a), "l"(b), "l"(c));
    return d;
}
__device__ __forceinline__ u64 bcast2(float v) {
    u64 d; unsigned r = __float_as_uint(v);
    asm("mov.b64 %0, {%1, %1};" : "=l"(d) : "r"(r));
    return d;
}
__device__ __forceinline__ void unpk(u64 d, float& x, float& y) {
    unsigned a, b;
    asm("mov.b64 {%0, %1}, %2;" : "=r"(a), "=r"(b) : "l"(d));
    x = __uint_as_float(a); y = __uint_as_float(b);
}

// ---- dynamic shared layout (float offsets) ----
#define FCS   0        // fc_w: 32 rows x 160 (136 used; n-pair of a warp sits in one 128B line)
#define W1S   5120     // 8x16
#define B1S   5248     // 16
#define W2S   5264     // 16x32
#define B2S   5776     // 32
#define W3S   5808     // 32x32
#define B3S   6832     // 32
#define ZS    6864     // 16 graphs x 36
#define ARENA 7440     // 272 rows x 36 floats (exchange + out staging)
#define SHFLOATS 17232 // 68928 bytes per block

extern __shared__ float sh[];

__global__ void __launch_bounds__(TPB, 2)
gnn_fused(const float* __restrict__ z,
          const float* __restrict__ fc_w, const float* __restrict__ fc_b,
          const float* __restrict__ w1,   const float* __restrict__ b1,
          const float* __restrict__ w2,   const float* __restrict__ b2,
          const float* __restrict__ w3,   const float* __restrict__ b3,
          float* __restrict__ out)
{
    const int tid = threadIdx.x;

    // ---------------- stage weights + z into shared ----------------
    for (int i = tid; i < 4352; i += TPB) {            // fc_w rows padded 136->160
        int k = i / 136, c = i - k * 136;
        sh[FCS + k * 160 + c] = fc_w[i];
    }
    for (int i = tid; i < 128;  i += TPB) sh[W1S + i] = w1[i];
    for (int i = tid; i < 512;  i += TPB) sh[W2S + i] = w2[i];
    for (int i = tid; i < 1024; i += TPB) sh[W3S + i] = w3[i];
    if (tid < 16)                         sh[B1S + tid] = b1[tid];
    else if (tid >= 32 && tid < 64)       sh[B2S + tid - 32] = b2[tid - 32];
    else if (tid >= 64 && tid < 96)       sh[B3S + tid - 64] = b3[tid - 64];
    {
        const float* zblk = z + (size_t)blockIdx.x * (NG * 32);
        for (int i = tid; i < NG * 32; i += TPB)
            sh[ZS + (i >> 5) * 36 + (i & 31)] = zblk[i];
    }
    __syncthreads();

    // thread = node n of graph g; warp holds 2 nodes x 16 graphs -> weight loads broadcast
    const int n  = tid >> 4;
    const int g  = tid & 15;
    const int rp = (n == NNODE - 1) ? g       : tid + 16;  // row of node (n+1)%17
    const int rm = (n == 0)         ? 256 + g : tid - 16;  // row of node (n-1)%17
    const float s3 = (1.0f / 3.0f);

    // ================= FC: x0 = z @ fc_w[:, 8n:8n+8] + fc_b =================
    float x0f[8];
    {
        u64 acc[4];
        const u64* fb = (const u64*)fc_b + n * 4;
        #pragma unroll
        for (int i = 0; i < 4; i++) acc[i] = __ldg(fb + i);
        float zr[32];
        const float4* zp = (const float4*)(sh + ZS + g * 36);
        #pragma unroll
        for (int i = 0; i < 8; i++) {
            float4 v = zp[i];
            zr[4*i] = v.x; zr[4*i+1] = v.y; zr[4*i+2] = v.z; zr[4*i+3] = v.w;
        }
        #pragma unroll
        for (int k = 0; k < 32; k++) {
            u64 zz = bcast2(zr[k]);
            const ulonglong2* w = (const ulonglong2*)(sh + FCS + k * 160 + n * 8);
            ulonglong2 wa = w[0], wb = w[1];
            acc[0] = ffma2(zz, wa.x, acc[0]);
            acc[1] = ffma2(zz, wa.y, acc[1]);
            acc[2] = ffma2(zz, wb.x, acc[2]);
            acc[3] = ffma2(zz, wb.y, acc[3]);
        }
        #pragma unroll
        for (int i = 0; i < 4; i++) unpk(acc[i], x0f[2*i], x0f[2*i+1]);
    }
    {
        float4* row = (float4*)(sh + ARENA + tid * 36);
        row[0] = make_float4(x0f[0], x0f[1], x0f[2], x0f[3]);
        row[1] = make_float4(x0f[4], x0f[5], x0f[6], x0f[7]);
    }
    __syncthreads();
    float a0[8];
    {
        const float4* p = (const float4*)(sh + ARENA + rp * 36);
        const float4* m = (const float4*)(sh + ARENA + rm * 36);
        #pragma unroll
        for (int q = 0; q < 2; q++) {
            float4 pv = p[q], mv = m[q];
            a0[4*q+0] = (x0f[4*q+0] + pv.x + mv.x) * s3;
            a0[4*q+1] = (x0f[4*q+1] + pv.y + mv.y) * s3;
            a0[4*q+2] = (x0f[4*q+2] + pv.z + mv.z) * s3;
            a0[4*q+3] = (x0f[4*q+3] + pv.w + mv.w) * s3;
        }
    }
    __syncthreads();

    // ================= conv1: x1 = relu(a0 @ w1 + b1), 16 out =================
    float x1f[16];
    {
        u64 acc[8];
        const u64* bb = (const u64*)(sh + B1S);
        #pragma unroll
        for (int j = 0; j < 8; j++) acc[j] = bb[j];
        #pragma unroll
        for (int k = 0; k < 8; k++) {
            u64 av = bcast2(a0[k]);
            const ulonglong2* w = (const ulonglong2*)(sh + W1S + k * 16);
            #pragma unroll
            for (int q = 0; q < 4; q++) {
                ulonglong2 t = w[q];
                acc[2*q]   = ffma2(av, t.x, acc[2*q]);
                acc[2*q+1] = ffma2(av, t.y, acc[2*q+1]);
            }
        }
        #pragma unroll
        for (int j = 0; j < 8; j++) {
            float x, y; unpk(acc[j], x, y);
            x1f[2*j]   = fmaxf(x, 0.0f);
            x1f[2*j+1] = fmaxf(y, 0.0f);
        }
    }
    {
        float4* row = (float4*)(sh + ARENA + tid * 36);
        #pragma unroll
        for (int q = 0; q < 4; q++)
            row[q] = make_float4(x1f[4*q], x1f[4*q+1], x1f[4*q+2], x1f[4*q+3]);
    }
    __syncthreads();
    float a1[16];
    {
        const float4* p = (const float4*)(sh + ARENA + rp * 36);
        const float4* m = (const float4*)(sh + ARENA + rm * 36);
        #pragma unroll
        for (int q = 0; q < 4; q++) {
            float4 pv = p[q], mv = m[q];
            a1[4*q+0] = (x1f[4*q+0] + pv.x + mv.x) * s3;
            a1[4*q+1] = (x1f[4*q+1] + pv.y + mv.y) * s3;
            a1[4*q+2] = (x1f[4*q+2] + pv.z + mv.z) * s3;
            a1[4*q+3] = (x1f[4*q+3] + pv.w + mv.w) * s3;
        }
    }
    __syncthreads();

    // ================= conv2: x2 = relu(a1 @ w2 + b2), 32 out =================
    float x2f[32];
    {
        u64 acc[16];
        const u64* bb = (const u64*)(sh + B2S);
        #pragma unroll
        for (int j = 0; j < 16; j++) acc[j] = bb[j];
        #pragma unroll
        for (int k = 0; k < 16; k++) {
            u64 av = bcast2(a1[k]);
            const ulonglong2* w = (const ulonglong2*)(sh + W2S + k * 32);
            #pragma unroll
            for (int q = 0; q < 8; q++) {
                ulonglong2 t = w[q];
                acc[2*q]   = ffma2(av, t.x, acc[2*q]);
                acc[2*q+1] = ffma2(av, t.y, acc[2*q+1]);
            }
        }
        #pragma unroll
        for (int j = 0; j < 16; j++) {
            float x, y; unpk(acc[j], x, y);
            x2f[2*j]   = fmaxf(x, 0.0f);
            x2f[2*j+1] = fmaxf(y, 0.0f);
        }
    }
    {
        float4* row = (float4*)(sh + ARENA + tid * 36);
        #pragma unroll
        for (int q = 0; q < 8; q++)
            row[q] = make_float4(x2f[4*q], x2f[4*q+1], x2f[4*q+2], x2f[4*q+3]);
    }
    __syncthreads();
    float a2[32];
    {
        const float4* p = (const float4*)(sh + ARENA + rp * 36);
        const float4* m = (const float4*)(sh + ARENA + rm * 36);
        #pragma unroll
        for (int q = 0; q < 8; q++) {
            float4 pv = p[q], mv = m[q];
            a2[4*q+0] = (x2f[4*q+0] + pv.x + mv.x) * s3;
            a2[4*q+1] = (x2f[4*q+1] + pv.y + mv.y) * s3;
            a2[4*q+2] = (x2f[4*q+2] + pv.z + mv.z) * s3;
            a2[4*q+3] = (x2f[4*q+3] + pv.w + mv.w) * s3;
        }
    }
    __syncthreads();

    // ================= conv3: out = a2 @ w3 + b3, 32 out (no relu) ============
    {
        u64 acc[16];
        const u64* bb = (const u64*)(sh + B3S);
        #pragma unroll
        for (int j = 0; j < 16; j++) acc[j] = bb[j];
        #pragma unroll
        for (int k = 0; k < 32; k++) {
            u64 av = bcast2(a2[k]);
            const ulonglong2* w = (const ulonglong2*)(sh + W3S + k * 32);
            #pragma unroll
            for (int q = 0; q < 8; q++) {
                ulonglong2 t = w[q];
                acc[2*q]   = ffma2(av, t.x, acc[2*q]);
                acc[2*q+1] = ffma2(av, t.y, acc[2*q+1]);
            }
        }
        float of[32];
        #pragma unroll
        for (int j = 0; j < 16; j++) unpk(acc[j], of[2*j], of[2*j+1]);
        // stage in out layout: row = g*17 + n
        float4* row = (float4*)(sh + ARENA + (g * 17 + n) * 36);
        #pragma unroll
        for (int q = 0; q < 8; q++)
            row[q] = make_float4(of[4*q], of[4*q+1], of[4*q+2], of[4*q+3]);
    }
    __syncthreads();

    // coalesced global write: 16*17*32 floats contiguous per block
    float4* og = (float4*)(out + (size_t)blockIdx.x * (NG * NNODE * 32));
    #pragma unroll
    for (int it = 0; it < 8; it++) {
        int q = tid + it * TPB;                 // 0 .. 2175
        int row = q >> 3, c = q & 7;
        og[q] = *(const float4*)(sh + ARENA + row * 36 + c * 4);
    }
}

extern "C" void kernel_launch(void* const* d_in, const int* in_sizes, int n_in,
                              void* d_out, int out_size) {
    const float* z    = (const float*)d_in[0];
    // d_in[1] = edge_index: fixed ring, degree==3 everywhere -> norm==1/3; unused
    const float* fc_w = (const float*)d_in[2];
    const float* fc_b = (const float*)d_in[3];
    const float* w1   = (const float*)d_in[4];
    const float* b1   = (const float*)d_in[5];
    const float* w2   = (const float*)d_in[6];
    const float* b2   = (const float*)d_in[7];
    const float* w3   = (const float*)d_in[8];
    const float* b3   = (const float*)d_in[9];

    cudaFuncSetAttribute(gnn_fused, cudaFuncAttributeMaxDynamicSharedMemorySize,
                         SHFLOATS * 4);

    const int B    = in_sizes[0] / 32;      // 65536 graphs
    const int grid = B / NG;                // 4096 blocks
    gnn_fused<<<grid, TPB, SHFLOATS * 4>>>(z, fc_w, fc_b, w1, b1, w2, b2, w3, b3,
                                           (float*)d_out);
}

// round 6
// speedup vs baseline: 1.1220x; 1.1220x over previous
#include <cuda_runtime.h>

#define NNODE 17
#define TPB   272      // 17 nodes x 16 graph-lanes
#define NG    32       // graphs per block: 2 graph-sets per thread (s = 0,1)

typedef unsigned long long u64;

// packed fp32x2 FMA (Blackwell); ptxas never auto-fuses this from C++
__device__ __forceinline__ u64 ffma2(u64 a, u64 b, u64 c) {
    u64 d;
    asm("fma.rn.f32x2 %0, %1, %2, %3;" : "=l"(d) : "l"(a), "l"(b), "l"(c));
    return d;
}
__device__ __forceinline__ u64 bcast2(float v) {
    u64 d; unsigned r = __float_as_uint(v);
    asm("mov.b64 %0, {%1, %1};" : "=l"(d) : "r"(r));
    return d;
}
__device__ __forceinline__ void unpk(u64 d, float& x, float& y) {
    unsigned a, b;
    asm("mov.b64 {%0, %1}, %2;" : "=r"(a), "=r"(b) : "l"(d));
    x = __uint_as_float(a); y = __uint_as_float(b);
}

// ---- dynamic shared layout (float offsets) ----
#define FCS   0        // fc_w: 32 rows x 160 (136 used; warp's n-pair in one 128B line)
#define W1S   5120     // 8x16
#define B1S   5248     // 16
#define W2S   5264     // 16x32
#define B2S   5776     // 32
#define W3S   5808     // 32x32
#define B3S   6832     // 32
#define ZS    6864     // 32 graphs x 36
#define ARENA 8016     // 544 rows x 36 floats (exchange + out staging)
#define SHFLOATS 27600 // 110400 bytes per block (x2 blocks = 220.8KB <= 228KB/SM)

extern __shared__ float sh[];

__global__ void __launch_bounds__(TPB, 2)
gnn_fused(const float* __restrict__ z,
          const float* __restrict__ fc_w, const float* __restrict__ fc_b,
          const float* __restrict__ w1,   const float* __restrict__ b1,
          const float* __restrict__ w2,   const float* __restrict__ b2,
          const float* __restrict__ w3,   const float* __restrict__ b3,
          float* __restrict__ out)
{
    const int tid = threadIdx.x;

    // ---------------- stage weights + z into shared ----------------
    for (int i = tid; i < 4352; i += TPB) {            // fc_w rows padded 136->160
        int k = i / 136, c = i - k * 136;
        sh[FCS + k * 160 + c] = fc_w[i];
    }
    for (int i = tid; i < 128;  i += TPB) sh[W1S + i] = w1[i];
    for (int i = tid; i < 512;  i += TPB) sh[W2S + i] = w2[i];
    for (int i = tid; i < 1024; i += TPB) sh[W3S + i] = w3[i];
    if (tid < 16)                         sh[B1S + tid] = b1[tid];
    else if (tid >= 32 && tid < 64)       sh[B2S + tid - 32] = b2[tid - 32];
    else if (tid >= 64 && tid < 96)       sh[B3S + tid - 64] = b3[tid - 64];
    {
        const float* zblk = z + (size_t)blockIdx.x * (NG * 32);
        for (int i = tid; i < NG * 32; i += TPB)
            sh[ZS + (i >> 5) * 36 + (i & 31)] = zblk[i];
    }
    __syncthreads();

    // thread = node n, graphs g and g+16; warp holds 2 nodes x 16 lanes -> weight
    // loads are warp-uniform broadcasts
    const int n  = tid >> 4;
    const int g  = tid & 15;
    const int rp = (n == NNODE - 1) ? g       : tid + 16;  // row of node (n+1)%17
    const int rm = (n == 0)         ? 256 + g : tid - 16;  // row of node (n-1)%17
    const float s3 = (1.0f / 3.0f);

    // ================= FC: x0 = z @ fc_w[:, 8n:8n+8] + fc_b ==================
    // both graph-sets interleaved over ONE weight stream
    float x0f[2][8];
    {
        float zr[2][32];
        #pragma unroll
        for (int s = 0; s < 2; s++) {
            const float4* zp = (const float4*)(sh + ZS + (g + 16 * s) * 36);
            #pragma unroll
            for (int i = 0; i < 8; i++) {
                float4 v = zp[i];
                zr[s][4*i] = v.x; zr[s][4*i+1] = v.y; zr[s][4*i+2] = v.z; zr[s][4*i+3] = v.w;
            }
        }
        u64 acc[2][4];
        {
            const u64* fb = (const u64*)fc_b + n * 4;
            #pragma unroll
            for (int i = 0; i < 4; i++) { u64 b = __ldg(fb + i); acc[0][i] = b; acc[1][i] = b; }
        }
        #pragma unroll
        for (int k = 0; k < 32; k++) {
            const ulonglong2* w = (const ulonglong2*)(sh + FCS + k * 160 + n * 8);
            ulonglong2 wa = w[0], wb = w[1];
            #pragma unroll
            for (int s = 0; s < 2; s++) {
                u64 zz = bcast2(zr[s][k]);
                acc[s][0] = ffma2(zz, wa.x, acc[s][0]);
                acc[s][1] = ffma2(zz, wa.y, acc[s][1]);
                acc[s][2] = ffma2(zz, wb.x, acc[s][2]);
                acc[s][3] = ffma2(zz, wb.y, acc[s][3]);
            }
        }
        #pragma unroll
        for (int s = 0; s < 2; s++)
            #pragma unroll
            for (int i = 0; i < 4; i++) unpk(acc[s][i], x0f[s][2*i], x0f[s][2*i+1]);
    }
    #pragma unroll
    for (int s = 0; s < 2; s++) {
        float4* row = (float4*)(sh + ARENA + (s * 272 + tid) * 36);
        row[0] = make_float4(x0f[s][0], x0f[s][1], x0f[s][2], x0f[s][3]);
        row[1] = make_float4(x0f[s][4], x0f[s][5], x0f[s][6], x0f[s][7]);
    }
    __syncthreads();
    float a0[2][8];
    #pragma unroll
    for (int s = 0; s < 2; s++) {
        const float4* p = (const float4*)(sh + ARENA + (s * 272 + rp) * 36);
        const float4* m = (const float4*)(sh + ARENA + (s * 272 + rm) * 36);
        #pragma unroll
        for (int q = 0; q < 2; q++) {
            float4 pv = p[q], mv = m[q];
            a0[s][4*q+0] = (x0f[s][4*q+0] + pv.x + mv.x) * s3;
            a0[s][4*q+1] = (x0f[s][4*q+1] + pv.y + mv.y) * s3;
            a0[s][4*q+2] = (x0f[s][4*q+2] + pv.z + mv.z) * s3;
            a0[s][4*q+3] = (x0f[s][4*q+3] + pv.w + mv.w) * s3;
        }
    }
    __syncthreads();

    // ================= conv1: x1 = relu(a0 @ w1 + b1), 16 out =================
    float x1f[2][16];
    {
        u64 acc[2][8];
        const u64* bb = (const u64*)(sh + B1S);
        #pragma unroll
        for (int j = 0; j < 8; j++) { u64 b = bb[j]; acc[0][j] = b; acc[1][j] = b; }
        #pragma unroll
        for (int k = 0; k < 8; k++) {
            const ulonglong2* w = (const ulonglong2*)(sh + W1S + k * 16);
            #pragma unroll
            for (int q = 0; q < 4; q++) {
                ulonglong2 t = w[q];
                #pragma unroll
                for (int s = 0; s < 2; s++) {
                    u64 av = bcast2(a0[s][k]);
                    acc[s][2*q]   = ffma2(av, t.x, acc[s][2*q]);
                    acc[s][2*q+1] = ffma2(av, t.y, acc[s][2*q+1]);
                }
            }
        }
        #pragma unroll
        for (int s = 0; s < 2; s++)
            #pragma unroll
            for (int j = 0; j < 8; j++) {
                float x, y; unpk(acc[s][j], x, y);
                x1f[s][2*j]   = fmaxf(x, 0.0f);
                x1f[s][2*j+1] = fmaxf(y, 0.0f);
            }
    }
    #pragma unroll
    for (int s = 0; s < 2; s++) {
        float4* row = (float4*)(sh + ARENA + (s * 272 + tid) * 36);
        #pragma unroll
        for (int q = 0; q < 4; q++)
            row[q] = make_float4(x1f[s][4*q], x1f[s][4*q+1], x1f[s][4*q+2], x1f[s][4*q+3]);
    }
    __syncthreads();
    float a1[2][16];
    #pragma unroll
    for (int s = 0; s < 2; s++) {
        const float4* p = (const float4*)(sh + ARENA + (s * 272 + rp) * 36);
        const float4* m = (const float4*)(sh + ARENA + (s * 272 + rm) * 36);
        #pragma unroll
        for (int q = 0; q < 4; q++) {
            float4 pv = p[q], mv = m[q];
            a1[s][4*q+0] = (x1f[s][4*q+0] + pv.x + mv.x) * s3;
            a1[s][4*q+1] = (x1f[s][4*q+1] + pv.y + mv.y) * s3;
            a1[s][4*q+2] = (x1f[s][4*q+2] + pv.z + mv.z) * s3;
            a1[s][4*q+3] = (x1f[s][4*q+3] + pv.w + mv.w) * s3;
        }
    }
    __syncthreads();

    // ====== conv2: x2 = relu(a1 @ w2 + b2), 32 out, computed in j-halves ======
    // results go straight to shared; a2 rebuilt from shared (keeps regs low)
    #pragma unroll
    for (int h = 0; h < 2; h++) {
        u64 acc[2][8];
        const u64* bb = (const u64*)(sh + B2S + h * 16);
        #pragma unroll
        for (int j = 0; j < 8; j++) { u64 b = bb[j]; acc[0][j] = b; acc[1][j] = b; }
        #pragma unroll
        for (int k = 0; k < 16; k++) {
            const ulonglong2* w = (const ulonglong2*)(sh + W2S + k * 32 + h * 16);
            #pragma unroll
            for (int q = 0; q < 4; q++) {
                ulonglong2 t = w[q];
                #pragma unroll
                for (int s = 0; s < 2; s++) {
                    u64 av = bcast2(a1[s][k]);
                    acc[s][2*q]   = ffma2(av, t.x, acc[s][2*q]);
                    acc[s][2*q+1] = ffma2(av, t.y, acc[s][2*q+1]);
                }
            }
        }
        #pragma unroll
        for (int s = 0; s < 2; s++) {
            float xf[16];
            #pragma unroll
            for (int j = 0; j < 8; j++) {
                float x, y; unpk(acc[s][j], x, y);
                xf[2*j]   = fmaxf(x, 0.0f);
                xf[2*j+1] = fmaxf(y, 0.0f);
            }
            float4* row = (float4*)(sh + ARENA + (s * 272 + tid) * 36 + h * 16);
            #pragma unroll
            for (int q = 0; q < 4; q++)
                row[q] = make_float4(xf[4*q], xf[4*q+1], xf[4*q+2], xf[4*q+3]);
        }
    }
    __syncthreads();
    float a2[2][32];
    #pragma unroll
    for (int s = 0; s < 2; s++) {
        const float4* o = (const float4*)(sh + ARENA + (s * 272 + tid) * 36);
        const float4* p = (const float4*)(sh + ARENA + (s * 272 + rp) * 36);
        const float4* m = (const float4*)(sh + ARENA + (s * 272 + rm) * 36);
        #pragma unroll
        for (int q = 0; q < 8; q++) {
            float4 ov = o[q], pv = p[q], mv = m[q];
            a2[s][4*q+0] = (ov.x + pv.x + mv.x) * s3;
            a2[s][4*q+1] = (ov.y + pv.y + mv.y) * s3;
            a2[s][4*q+2] = (ov.z + pv.z + mv.z) * s3;
            a2[s][4*q+3] = (ov.w + pv.w + mv.w) * s3;
        }
    }
    __syncthreads();

    // ====== conv3: out = a2 @ w3 + b3, 32 out (no relu), j-halves =============
    #pragma unroll
    for (int h = 0; h < 2; h++) {
        u64 acc[2][8];
        const u64* bb = (const u64*)(sh + B3S + h * 16);
        #pragma unroll
        for (int j = 0; j < 8; j++) { u64 b = bb[j]; acc[0][j] = b; acc[1][j] = b; }
        #pragma unroll
        for (int k = 0; k < 32; k++) {
            const ulonglong2* w = (const ulonglong2*)(sh + W3S + k * 32 + h * 16);
            #pragma unroll
            for (int q = 0; q < 4; q++) {
                ulonglong2 t = w[q];
                #pragma unroll
                for (int s = 0; s < 2; s++) {
                    u64 av = bcast2(a2[s][k]);
                    acc[s][2*q]   = ffma2(av, t.x, acc[s][2*q]);
                    acc[s][2*q+1] = ffma2(av, t.y, acc[s][2*q+1]);
                }
            }
        }
        // stage in out layout: row = (g + 16s)*17 + n
        #pragma unroll
        for (int s = 0; s < 2; s++) {
            float of[16];
            #pragma unroll
            for (int j = 0; j < 8; j++) unpk(acc[s][j], of[2*j], of[2*j+1]);
            float4* row = (float4*)(sh + ARENA + ((g + 16 * s) * 17 + n) * 36 + h * 16);
            #pragma unroll
            for (int q = 0; q < 4; q++)
                row[q] = make_float4(of[4*q], of[4*q+1], of[4*q+2], of[4*q+3]);
        }
    }
    __syncthreads();

    // coalesced global write: 32*17*32 floats contiguous per block
    float4* og = (float4*)(out + (size_t)blockIdx.x * (NG * NNODE * 32));
    #pragma unroll
    for (int it = 0; it < 16; it++) {
        int q = tid + it * TPB;                 // 0 .. 4351
        int row = q >> 3, c = q & 7;
        og[q] = *(const float4*)(sh + ARENA + row * 36 + c * 4);
    }
}

extern "C" void kernel_launch(void* const* d_in, const int* in_sizes, int n_in,
                              void* d_out, int out_size) {
    const float* z    = (const float*)d_in[0];
    // d_in[1] = edge_index: fixed ring, degree==3 everywhere -> norm==1/3; unused
    const float* fc_w = (const float*)d_in[2];
    const float* fc_b = (const float*)d_in[3];
    const float* w1   = (const float*)d_in[4];
    const float* b1   = (const float*)d_in[5];
    const float* w2   = (const float*)d_in[6];
    const float* b2   = (const float*)d_in[7];
    const float* w3   = (const float*)d_in[8];
    const float* b3   = (const float*)d_in[9];

    cudaFuncSetAttribute(gnn_fused, cudaFuncAttributeMaxDynamicSharedMemorySize,
                         SHFLOATS * 4);

    const int B    = in_sizes[0] / 32;      // 65536 graphs
    const int grid = B / NG;                // 2048 blocks
    gnn_fused<<<grid, TPB, SHFLOATS * 4>>>(z, fc_w, fc_b, w1, b1, w2, b2, w3, b3,
                                           (float*)d_out);
}

// round 7
// speedup vs baseline: 1.1245x; 1.0022x over previous
#include <cuda_runtime.h>

#define NNODE 17
#define TPB   272      // 17 nodes x 16 graph-lanes
#define NG    32       // graphs per block: 2 graph-sets per thread (s = 0,1)

typedef unsigned long long u64;

// packed fp32x2 ops (Blackwell); ptxas never auto-fuses these from C++
__device__ __forceinline__ u64 ffma2(u64 a, u64 b, u64 c) {
    u64 d;
    asm("fma.rn.f32x2 %0, %1, %2, %3;" : "=l"(d) : "l"(a), "l"(b), "l"(c));
    return d;
}
__device__ __forceinline__ u64 add2(u64 a, u64 b) {
    u64 d;
    asm("add.rn.f32x2 %0, %1, %2;" : "=l"(d) : "l"(a), "l"(b));
    return d;
}
__device__ __forceinline__ u64 mul2(u64 a, u64 b) {
    u64 d;
    asm("mul.rn.f32x2 %0, %1, %2;" : "=l"(d) : "l"(a), "l"(b));
    return d;
}
__device__ __forceinline__ u64 bcast2(float v) {
    u64 d; unsigned r = __float_as_uint(v);
    asm("mov.b64 %0, {%1, %1};" : "=l"(d) : "r"(r));
    return d;
}
__device__ __forceinline__ u64 pack2(float x, float y) {
    u64 d;
    asm("mov.b64 %0, {%1, %2};" : "=l"(d) : "r"(__float_as_uint(x)), "r"(__float_as_uint(y)));
    return d;
}
__device__ __forceinline__ void unpk(u64 d, float& x, float& y) {
    unsigned a, b;
    asm("mov.b64 {%0, %1}, %2;" : "=r"(a), "=r"(b) : "l"(d));
    x = __uint_as_float(a); y = __uint_as_float(b);
}

// ---- dynamic shared layout (float offsets) ----
#define FCS   0        // fc_w: 32 rows x 160 (136 used; warp's n-pair in one 128B line)
#define W1S   5120     // 8x16
#define B1S   5248     // 16
#define W2S   5264     // 16x32
#define B2S   5776     // 32
#define W3S   5808     // 32x32
#define B3S   6832     // 32
#define ZS    6864     // 32 graphs x 36
#define ARENA 8016     // 544 rows x 36 floats (exchange)
#define SHFLOATS 27600 // 110400 bytes per block (x2 blocks <= 228KB/SM)

extern __shared__ float sh[];

__global__ void __launch_bounds__(TPB, 2)
gnn_fused(const float* __restrict__ z,
          const float* __restrict__ fc_w, const float* __restrict__ fc_b,
          const float* __restrict__ w1,   const float* __restrict__ b1,
          const float* __restrict__ w2,   const float* __restrict__ b2,
          const float* __restrict__ w3,   const float* __restrict__ b3,
          float* __restrict__ out)
{
    const int tid = threadIdx.x;

    // ---------------- stage weights + z into shared ----------------
    for (int i = tid; i < 4352; i += TPB) {            // fc_w rows padded 136->160
        int k = i / 136, c = i - k * 136;
        sh[FCS + k * 160 + c] = fc_w[i];
    }
    for (int i = tid; i < 128;  i += TPB) sh[W1S + i] = w1[i];
    for (int i = tid; i < 512;  i += TPB) sh[W2S + i] = w2[i];
    for (int i = tid; i < 1024; i += TPB) sh[W3S + i] = w3[i];
    if (tid < 16)                         sh[B1S + tid] = b1[tid];
    else if (tid >= 32 && tid < 64)       sh[B2S + tid - 32] = b2[tid - 32];
    else if (tid >= 64 && tid < 96)       sh[B3S + tid - 64] = b3[tid - 64];
    {
        const float* zblk = z + (size_t)blockIdx.x * (NG * 32);
        for (int i = tid; i < NG * 32; i += TPB)
            sh[ZS + (i >> 5) * 36 + (i & 31)] = zblk[i];
    }
    __syncthreads();

    // thread = node n, graphs g and g+16; warp holds 2 nodes x 16 lanes
    const int n  = tid >> 4;
    const int g  = tid & 15;
    const int rp = (n == NNODE - 1) ? g       : tid + 16;  // row of node (n+1)%17
    const int rm = (n == 0)         ? 256 + g : tid - 16;  // row of node (n-1)%17
    const u64 third2 = bcast2(1.0f / 3.0f);

    // ================= FC: x0 = z @ fc_w[:, 8n:8n+8] + fc_b ==================
    u64 x0p[2][4];                                      // packed x0 (8 floats = 4 u64)
    {
        float zr[2][32];
        #pragma unroll
        for (int s = 0; s < 2; s++) {
            const float4* zp = (const float4*)(sh + ZS + (g + 16 * s) * 36);
            #pragma unroll
            for (int i = 0; i < 8; i++) {
                float4 v = zp[i];
                zr[s][4*i] = v.x; zr[s][4*i+1] = v.y; zr[s][4*i+2] = v.z; zr[s][4*i+3] = v.w;
            }
        }
        {
            const u64* fb = (const u64*)fc_b + n * 4;
            #pragma unroll
            for (int i = 0; i < 4; i++) { u64 b = __ldg(fb + i); x0p[0][i] = b; x0p[1][i] = b; }
        }
        #pragma unroll
        for (int k = 0; k < 32; k++) {
            const ulonglong2* w = (const ulonglong2*)(sh + FCS + k * 160 + n * 8);
            ulonglong2 wa = w[0], wb = w[1];
            #pragma unroll
            for (int s = 0; s < 2; s++) {
                u64 zz = bcast2(zr[s][k]);
                x0p[s][0] = ffma2(zz, wa.x, x0p[s][0]);
                x0p[s][1] = ffma2(zz, wa.y, x0p[s][1]);
                x0p[s][2] = ffma2(zz, wb.x, x0p[s][2]);
                x0p[s][3] = ffma2(zz, wb.y, x0p[s][3]);
            }
        }
    }
    #pragma unroll
    for (int s = 0; s < 2; s++) {
        ulonglong2* row = (ulonglong2*)(sh + ARENA + (s * 272 + tid) * 36);
        row[0] = make_ulonglong2(x0p[s][0], x0p[s][1]);
        row[1] = make_ulonglong2(x0p[s][2], x0p[s][3]);
    }
    __syncthreads();
    float a0[2][8];
    #pragma unroll
    for (int s = 0; s < 2; s++) {
        const ulonglong2* p = (const ulonglong2*)(sh + ARENA + (s * 272 + rp) * 36);
        const ulonglong2* m = (const ulonglong2*)(sh + ARENA + (s * 272 + rm) * 36);
        #pragma unroll
        for (int q = 0; q < 2; q++) {
            ulonglong2 pv = p[q], mv = m[q];
            u64 t0 = mul2(add2(add2(x0p[s][2*q],   pv.x), mv.x), third2);
            u64 t1 = mul2(add2(add2(x0p[s][2*q+1], pv.y), mv.y), third2);
            unpk(t0, a0[s][4*q+0], a0[s][4*q+1]);
            unpk(t1, a0[s][4*q+2], a0[s][4*q+3]);
        }
    }
    __syncthreads();

    // ================= conv1: x1 = relu(a0 @ w1 + b1), 16 out =================
    u64 x1p[2][8];
    {
        u64 acc[2][8];
        const u64* bb = (const u64*)(sh + B1S);
        #pragma unroll
        for (int j = 0; j < 8; j++) { u64 b = bb[j]; acc[0][j] = b; acc[1][j] = b; }
        #pragma unroll
        for (int k = 0; k < 8; k++) {
            const ulonglong2* w = (const ulonglong2*)(sh + W1S + k * 16);
            #pragma unroll
            for (int q = 0; q < 4; q++) {
                ulonglong2 t = w[q];
                #pragma unroll
                for (int s = 0; s < 2; s++) {
                    u64 av = bcast2(a0[s][k]);
                    acc[s][2*q]   = ffma2(av, t.x, acc[s][2*q]);
                    acc[s][2*q+1] = ffma2(av, t.y, acc[s][2*q+1]);
                }
            }
        }
        #pragma unroll
        for (int s = 0; s < 2; s++)
            #pragma unroll
            for (int j = 0; j < 8; j++) {
                float x, y; unpk(acc[s][j], x, y);
                x1p[s][j] = pack2(fmaxf(x, 0.0f), fmaxf(y, 0.0f));
            }
    }
    #pragma unroll
    for (int s = 0; s < 2; s++) {
        ulonglong2* row = (ulonglong2*)(sh + ARENA + (s * 272 + tid) * 36);
        #pragma unroll
        for (int q = 0; q < 4; q++)
            row[q] = make_ulonglong2(x1p[s][2*q], x1p[s][2*q+1]);
    }
    __syncthreads();
    float a1[2][16];
    #pragma unroll
    for (int s = 0; s < 2; s++) {
        const ulonglong2* p = (const ulonglong2*)(sh + ARENA + (s * 272 + rp) * 36);
        const ulonglong2* m = (const ulonglong2*)(sh + ARENA + (s * 272 + rm) * 36);
        #pragma unroll
        for (int q = 0; q < 4; q++) {
            ulonglong2 pv = p[q], mv = m[q];
            u64 t0 = mul2(add2(add2(x1p[s][2*q],   pv.x), mv.x), third2);
            u64 t1 = mul2(add2(add2(x1p[s][2*q+1], pv.y), mv.y), third2);
            unpk(t0, a1[s][4*q+0], a1[s][4*q+1]);
            unpk(t1, a1[s][4*q+2], a1[s][4*q+3]);
        }
    }
    __syncthreads();

    // ====== conv2: x2 = relu(a1 @ w2 + b2), 32 out, computed in j-halves ======
    #pragma unroll
    for (int h = 0; h < 2; h++) {
        u64 acc[2][8];
        const u64* bb = (const u64*)(sh + B2S + h * 16);
        #pragma unroll
        for (int j = 0; j < 8; j++) { u64 b = bb[j]; acc[0][j] = b; acc[1][j] = b; }
        #pragma unroll
        for (int k = 0; k < 16; k++) {
            const ulonglong2* w = (const ulonglong2*)(sh + W2S + k * 32 + h * 16);
            #pragma unroll
            for (int q = 0; q < 4; q++) {
                ulonglong2 t = w[q];
                #pragma unroll
                for (int s = 0; s < 2; s++) {
                    u64 av = bcast2(a1[s][k]);
                    acc[s][2*q]   = ffma2(av, t.x, acc[s][2*q]);
                    acc[s][2*q+1] = ffma2(av, t.y, acc[s][2*q+1]);
                }
            }
        }
        #pragma unroll
        for (int s = 0; s < 2; s++) {
            u64 xp[8];
            #pragma unroll
            for (int j = 0; j < 8; j++) {
                float x, y; unpk(acc[s][j], x, y);
                xp[j] = pack2(fmaxf(x, 0.0f), fmaxf(y, 0.0f));
            }
            ulonglong2* row = (ulonglong2*)(sh + ARENA + (s * 272 + tid) * 36 + h * 16);
            #pragma unroll
            for (int q = 0; q < 4; q++)
                row[q] = make_ulonglong2(xp[2*q], xp[2*q+1]);
        }
    }
    __syncthreads();
    float a2[2][32];
    #pragma unroll
    for (int s = 0; s < 2; s++) {
        const ulonglong2* o = (const ulonglong2*)(sh + ARENA + (s * 272 + tid) * 36);
        const ulonglong2* p = (const ulonglong2*)(sh + ARENA + (s * 272 + rp) * 36);
        const ulonglong2* m = (const ulonglong2*)(sh + ARENA + (s * 272 + rm) * 36);
        #pragma unroll
        for (int q = 0; q < 8; q++) {
            ulonglong2 ov = o[q], pv = p[q], mv = m[q];
            u64 t0 = mul2(add2(add2(ov.x, pv.x), mv.x), third2);
            u64 t1 = mul2(add2(add2(ov.y, pv.y), mv.y), third2);
            unpk(t0, a2[s][4*q+0], a2[s][4*q+1]);
            unpk(t1, a2[s][4*q+2], a2[s][4*q+3]);
        }
    }
    // no further arena writes -> no sync needed after this point

    // ====== conv3: out = a2 @ w3 + b3, direct STG epilogue, j-halves ==========
    float* oblk = out + (size_t)blockIdx.x * (NG * NNODE * 32);
    #pragma unroll
    for (int h = 0; h < 2; h++) {
        u64 acc[2][8];
        const u64* bb = (const u64*)(sh + B3S + h * 16);
        #pragma unroll
        for (int j = 0; j < 8; j++) { u64 b = bb[j]; acc[0][j] = b; acc[1][j] = b; }
        #pragma unroll
        for (int k = 0; k < 32; k++) {
            const ulonglong2* w = (const ulonglong2*)(sh + W3S + k * 32 + h * 16);
            #pragma unroll
            for (int q = 0; q < 4; q++) {
                ulonglong2 t = w[q];
                #pragma unroll
                for (int s = 0; s < 2; s++) {
                    u64 av = bcast2(a2[s][k]);
                    acc[s][2*q]   = ffma2(av, t.x, acc[s][2*q]);
                    acc[s][2*q+1] = ffma2(av, t.y, acc[s][2*q+1]);
                }
            }
        }
        // direct global store: row (g+16s)*17 + n, columns h*16 .. h*16+15
        #pragma unroll
        for (int s = 0; s < 2; s++) {
            ulonglong2* orow = (ulonglong2*)(oblk + ((g + 16 * s) * 17 + n) * 32 + h * 16);
            #pragma unroll
            for (int q = 0; q < 4; q++)
                orow[q] = make_ulonglong2(acc[s][2*q], acc[s][2*q+1]);
        }
    }
}

extern "C" void kernel_launch(void* const* d_in, const int* in_sizes, int n_in,
                              void* d_out, int out_size) {
    const float* z    = (const float*)d_in[0];
    // d_in[1] = edge_index: fixed ring, degree==3 everywhere -> norm==1/3; unused
    const float* fc_w = (const float*)d_in[2];
    const float* fc_b = (const float*)d_in[3];
    const float* w1   = (const float*)d_in[4];
    const float* b1   = (const float*)d_in[5];
    const float* w2   = (const float*)d_in[6];
    const float* b2   = (const float*)d_in[7];
    const float* w3   = (const float*)d_in[8];
    const float* b3   = (const float*)d_in[9];

    cudaFuncSetAttribute(gnn_fused, cudaFuncAttributeMaxDynamicSharedMemorySize,
                         SHFLOATS * 4);

    const int B    = in_sizes[0] / 32;      // 65536 graphs
    const int grid = B / NG;                // 2048 blocks
    gnn_fused<<<grid, TPB, SHFLOATS * 4>>>(z, fc_w, fc_b, w1, b1, w2, b2, w3, b3,
                                           (float*)d_out);
}